// round 3
// baseline (speedup 1.0000x reference)
#include <cuda_runtime.h>

#define D 8192
#define THREADS 512
#define NWARPS (THREADS / 32)           // 16
#define BUF 1024                        // candidate buffer (floats)

__global__ __launch_bounds__(THREADS, 2)
void sparsemax_kernel(const float* __restrict__ x, float* __restrict__ out, int nrows) {
    __shared__ float sbuf[BUF];          // candidates > max-1
    __shared__ float swarp[NWARPS];      // block max scratch
    __shared__ float sredf[NWARPS];      // fallback sum scratch
    __shared__ int   sredk[NWARPS];      // fallback count scratch
    __shared__ int   s_cnt;
    __shared__ float s_tau;
    __shared__ int   s_k;

    const int tid = threadIdx.x;
    const int lid = tid & 31;
    const int stride = gridDim.x;

    int r = blockIdx.x;
    if (r >= nrows) return;

    if (tid == 0) s_cnt = 0;

    // ---- prologue: load first row into current registers ----
    float4 c0, c1, c2, c3;
    {
        const float4* __restrict__ xin = reinterpret_cast<const float4*>(x + (size_t)r * D);
        c0 = __ldcs(&xin[tid]);
        c1 = __ldcs(&xin[tid + THREADS]);
        c2 = __ldcs(&xin[tid + 2 * THREADS]);
        c3 = __ldcs(&xin[tid + 3 * THREADS]);
    }

    while (true) {
        // ---- prefetch next row BEFORE any compute on current row ----
        const int rn = r + stride;
        const bool has_next = (rn < nrows);
        float4 n0, n1, n2, n3;
        if (has_next) {
            const float4* __restrict__ xn = reinterpret_cast<const float4*>(x + (size_t)rn * D);
            n0 = __ldcs(&xn[tid]);
            n1 = __ldcs(&xn[tid + THREADS]);
            n2 = __ldcs(&xn[tid + 2 * THREADS]);
            n3 = __ldcs(&xn[tid + 3 * THREADS]);
        }

        // ---- max reduction over current row ----
        float m = fmaxf(fmaxf(fmaxf(c0.x, c0.y), fmaxf(c0.z, c0.w)),
                        fmaxf(fmaxf(c1.x, c1.y), fmaxf(c1.z, c1.w)));
        m = fmaxf(m, fmaxf(fmaxf(c2.x, c2.y), fmaxf(c2.z, c2.w)));
        m = fmaxf(m, fmaxf(fmaxf(c3.x, c3.y), fmaxf(c3.z, c3.w)));
        #pragma unroll
        for (int o = 16; o > 0; o >>= 1)
            m = fmaxf(m, __shfl_xor_sync(0xffffffffu, m, o));
        if (lid == 0) swarp[tid >> 5] = m;
        __syncthreads();                         // barrier 1 (also covers s_cnt reset)

        float mm = swarp[lid & (NWARPS - 1)];
        #pragma unroll
        for (int o = NWARPS / 2; o > 0; o >>= 1)
            mm = fmaxf(mm, __shfl_xor_sync(0xffffffffu, mm, o));
        const float thr = mm - 1.0f;             // valid lower bound on tau*

        // ---- gather candidates {x > thr} (rare for gaussian rows) ----
        {
            float vals[16] = {c0.x, c0.y, c0.z, c0.w, c1.x, c1.y, c1.z, c1.w,
                              c2.x, c2.y, c2.z, c2.w, c3.x, c3.y, c3.z, c3.w};
            #pragma unroll
            for (int i = 0; i < 16; i++) {
                if (vals[i] > thr) {
                    int p = atomicAdd(&s_cnt, 1);
                    if (p < BUF) sbuf[p] = vals[i];
                }
            }
        }
        __syncthreads();                         // barrier 2
        const int cnt = s_cnt;

        if (cnt <= BUF) {
            // ---- Michelot fixed-point on the tiny candidate set (warp 0) ----
            if (tid < 32) {
                float tau = thr;
                int prev = -1;
                for (int it = 0; it < cnt + 2; it++) {
                    float s = 0.0f; int k = 0;
                    for (int j = tid; j < cnt; j += 32) {
                        float v = sbuf[j];
                        if (v > tau) { s += v; k++; }
                    }
                    #pragma unroll
                    for (int o = 16; o > 0; o >>= 1) {
                        s += __shfl_xor_sync(0xffffffffu, s, o);
                        k += __shfl_xor_sync(0xffffffffu, k, o);
                    }
                    tau = (s - 1.0f) / (float)k;
                    if (k == prev) break;        // active set stable -> fixed point
                    prev = k;
                }
                if (tid == 0) s_tau = tau;
            }
            __syncthreads();                     // barrier 3
        } else {
            // ---- Fallback: block-wide Michelot over register values ----
            float tau = thr;
            int prev = -1;
            for (int it = 0; it < D + 2; it++) {
                float s = 0.0f; int k = 0;
                float vals[16] = {c0.x, c0.y, c0.z, c0.w, c1.x, c1.y, c1.z, c1.w,
                                  c2.x, c2.y, c2.z, c2.w, c3.x, c3.y, c3.z, c3.w};
                #pragma unroll
                for (int i = 0; i < 16; i++)
                    if (vals[i] > tau) { s += vals[i]; k++; }
                #pragma unroll
                for (int o = 16; o > 0; o >>= 1) {
                    s += __shfl_xor_sync(0xffffffffu, s, o);
                    k += __shfl_xor_sync(0xffffffffu, k, o);
                }
                if (lid == 0) { sredf[tid >> 5] = s; sredk[tid >> 5] = k; }
                __syncthreads();
                if (tid == 0) {
                    float S = 0.0f; int K = 0;
                    #pragma unroll
                    for (int w = 0; w < NWARPS; w++) { S += sredf[w]; K += sredk[w]; }
                    s_tau = (S - 1.0f) / (float)K;
                    s_k = K;
                }
                __syncthreads();
                tau = s_tau;
                int K = s_k;
                if (K == prev) break;
                prev = K;
            }
            __syncthreads();                     // barrier 3 (fallback)
        }

        // reset s_cnt for next iteration: next gather is after next barrier 1
        if (tid == 0) s_cnt = 0;

        // ---- write relu(x - tau) straight from registers (streaming) ----
        const float tau = s_tau;
        float4 w0 = c0, w1 = c1, w2 = c2, w3 = c3;
        w0.x = fmaxf(w0.x - tau, 0.0f); w0.y = fmaxf(w0.y - tau, 0.0f);
        w0.z = fmaxf(w0.z - tau, 0.0f); w0.w = fmaxf(w0.w - tau, 0.0f);
        w1.x = fmaxf(w1.x - tau, 0.0f); w1.y = fmaxf(w1.y - tau, 0.0f);
        w1.z = fmaxf(w1.z - tau, 0.0f); w1.w = fmaxf(w1.w - tau, 0.0f);
        w2.x = fmaxf(w2.x - tau, 0.0f); w2.y = fmaxf(w2.y - tau, 0.0f);
        w2.z = fmaxf(w2.z - tau, 0.0f); w2.w = fmaxf(w2.w - tau, 0.0f);
        w3.x = fmaxf(w3.x - tau, 0.0f); w3.y = fmaxf(w3.y - tau, 0.0f);
        w3.z = fmaxf(w3.z - tau, 0.0f); w3.w = fmaxf(w3.w - tau, 0.0f);
        float4* __restrict__ xout = reinterpret_cast<float4*>(out + (size_t)r * D);
        __stcs(&xout[tid],               w0);
        __stcs(&xout[tid + THREADS],     w1);
        __stcs(&xout[tid + 2 * THREADS], w2);
        __stcs(&xout[tid + 3 * THREADS], w3);

        if (!has_next) break;
        // consume prefetch (scoreboard wait lands here, after full compute+store)
        c0 = n0; c1 = n1; c2 = n2; c3 = n3;
        r = rn;
    }
}

extern "C" void kernel_launch(void* const* d_in, const int* in_sizes, int n_in,
                              void* d_out, int out_size) {
    const float* x = (const float*)d_in[0];
    float* out = (float*)d_out;
    const int rows = in_sizes[0] / D;   // 8192

    int dev = 0;
    cudaGetDevice(&dev);
    int nsm = 148;
    cudaDeviceGetAttribute(&nsm, cudaDevAttrMultiProcessorCount, dev);
    int grid = nsm * 2;                 // 2 CTAs/SM, persistent, static strided rows
    if (grid > rows) grid = rows;

    sparsemax_kernel<<<grid, THREADS>>>(x, out, rows);
}

// round 4
// speedup vs baseline: 1.1130x; 1.1130x over previous
#include <cuda_runtime.h>
#include <cstdint>

#define D 8192
#define THREADS 512
#define NWARPS (THREADS / 32)           // 16
#define BUF 1024                        // candidate buffer (floats)
#define ROW_BYTES (D * 4)               // 32768

// ---- PTX helpers (sm_90+/sm_103a) ----
__device__ __forceinline__ uint32_t smem_u32(const void* p) {
    return (uint32_t)__cvta_generic_to_shared(p);
}
__device__ __forceinline__ void mbar_init(uint32_t mbar, uint32_t count) {
    asm volatile("mbarrier.init.shared::cta.b64 [%0], %1;" :: "r"(mbar), "r"(count) : "memory");
}
__device__ __forceinline__ void mbar_expect_tx(uint32_t mbar, uint32_t bytes) {
    asm volatile("mbarrier.arrive.expect_tx.shared::cta.b64 _, [%0], %1;"
                 :: "r"(mbar), "r"(bytes) : "memory");
}
__device__ __forceinline__ void tma_1d_g2s(uint32_t dst_smem, const void* src_gmem,
                                           uint32_t bytes, uint32_t mbar) {
    asm volatile("cp.async.bulk.shared::cluster.global.mbarrier::complete_tx::bytes "
                 "[%0], [%1], %2, [%3];"
                 :: "r"(dst_smem), "l"(src_gmem), "r"(bytes), "r"(mbar) : "memory");
}
__device__ __forceinline__ void mbar_wait(uint32_t mbar, uint32_t parity) {
    uint32_t done;
    asm volatile("{\n\t.reg .pred p;\n\t"
                 "mbarrier.try_wait.parity.acquire.cta.shared::cta.b64 p, [%1], %2;\n\t"
                 "selp.b32 %0, 1, 0, p;\n\t}"
                 : "=r"(done) : "r"(mbar), "r"(parity) : "memory");
    if (!done) {
        asm volatile("{\n\t.reg .pred P1;\n"
                     "WL_%=:\n\t"
                     "mbarrier.try_wait.parity.acquire.cta.shared::cta.b64 P1, [%0], %1, 0x989680;\n\t"
                     "@P1 bra.uni WD_%=;\n\t"
                     "bra.uni WL_%=;\n"
                     "WD_%=:\n\t}"
                     :: "r"(mbar), "r"(parity) : "memory");
    }
}

extern __shared__ float srow[];          // dynamic: 2 * D floats = 64 KB (double buffer)

__global__ __launch_bounds__(THREADS, 3)
void sparsemax_kernel(const float* __restrict__ x, float* __restrict__ out, int nrows) {
    __shared__ float sbuf[BUF];          // candidates > max-1
    __shared__ float swarp[NWARPS];      // block max scratch
    __shared__ float sredf[NWARPS];      // fallback sum scratch
    __shared__ int   sredk[NWARPS];      // fallback count scratch
    __shared__ int   s_cnt;
    __shared__ float s_tau;
    __shared__ int   s_k;
    __shared__ __align__(8) uint64_t mbar_storage[2];

    const int tid = threadIdx.x;
    const int lid = tid & 31;
    const int stride = gridDim.x;
    int r = blockIdx.x;
    if (r >= nrows) return;

    const uint32_t mb0 = smem_u32(&mbar_storage[0]);
    const uint32_t mb1 = smem_u32(&mbar_storage[1]);
    const uint32_t ba0 = smem_u32(&srow[0]);
    const uint32_t ba1 = smem_u32(&srow[D]);

    if (tid == 0) {
        mbar_init(mb0, 1);
        mbar_init(mb1, 1);
        s_cnt = 0;
        asm volatile("fence.mbarrier_init.release.cluster;" ::: "memory");
    }
    __syncthreads();

    // ---- prologue: issue TMA for first row into buffer 0 ----
    if (tid == 0) {
        mbar_expect_tx(mb0, ROW_BYTES);
        tma_1d_g2s(ba0, x + (size_t)r * D, ROW_BYTES, mb0);
    }

    int cur = 0;
    uint32_t ph0 = 0u, ph1 = 0u;

    while (true) {
        const int rn = r + stride;
        const bool has_next = (rn < nrows);

        // ---- issue TMA for next row into the OTHER buffer (free since last iter) ----
        if (has_next && tid == 0) {
            const uint32_t mbn = (cur == 0) ? mb1 : mb0;
            const uint32_t ban = (cur == 0) ? ba1 : ba0;
            mbar_expect_tx(mbn, ROW_BYTES);
            tma_1d_g2s(ban, x + (size_t)rn * D, ROW_BYTES, mbn);
        }

        // ---- wait for current buffer, consume into registers ----
        if (cur == 0) { mbar_wait(mb0, ph0); ph0 ^= 1u; }
        else          { mbar_wait(mb1, ph1); ph1 ^= 1u; }

        const float4* sp = reinterpret_cast<const float4*>(srow + (size_t)cur * D);
        float4 c0 = sp[tid];
        float4 c1 = sp[tid + THREADS];
        float4 c2 = sp[tid + 2 * THREADS];
        float4 c3 = sp[tid + 3 * THREADS];
        __syncthreads();   // all threads done reading buf[cur] -> free for next issue

        // ---- max reduction ----
        float m = fmaxf(fmaxf(fmaxf(c0.x, c0.y), fmaxf(c0.z, c0.w)),
                        fmaxf(fmaxf(c1.x, c1.y), fmaxf(c1.z, c1.w)));
        m = fmaxf(m, fmaxf(fmaxf(c2.x, c2.y), fmaxf(c2.z, c2.w)));
        m = fmaxf(m, fmaxf(fmaxf(c3.x, c3.y), fmaxf(c3.z, c3.w)));
        #pragma unroll
        for (int o = 16; o > 0; o >>= 1)
            m = fmaxf(m, __shfl_xor_sync(0xffffffffu, m, o));
        if (lid == 0) swarp[tid >> 5] = m;
        __syncthreads();

        float mm = swarp[lid & (NWARPS - 1)];
        #pragma unroll
        for (int o = NWARPS / 2; o > 0; o >>= 1)
            mm = fmaxf(mm, __shfl_xor_sync(0xffffffffu, mm, o));
        const float thr = mm - 1.0f;     // valid lower bound on tau*

        // ---- gather candidates {x > thr} (rare for gaussian rows) ----
        {
            float vals[16] = {c0.x, c0.y, c0.z, c0.w, c1.x, c1.y, c1.z, c1.w,
                              c2.x, c2.y, c2.z, c2.w, c3.x, c3.y, c3.z, c3.w};
            #pragma unroll
            for (int i = 0; i < 16; i++) {
                if (vals[i] > thr) {
                    int p = atomicAdd(&s_cnt, 1);
                    if (p < BUF) sbuf[p] = vals[i];
                }
            }
        }
        __syncthreads();
        const int cnt = s_cnt;

        if (cnt <= BUF) {
            // ---- Michelot fixed-point on the tiny candidate set (warp 0) ----
            if (tid < 32) {
                float tau = thr;
                int prev = -1;
                for (int it = 0; it < cnt + 2; it++) {
                    float s = 0.0f; int k = 0;
                    for (int j = tid; j < cnt; j += 32) {
                        float v = sbuf[j];
                        if (v > tau) { s += v; k++; }
                    }
                    #pragma unroll
                    for (int o = 16; o > 0; o >>= 1) {
                        s += __shfl_xor_sync(0xffffffffu, s, o);
                        k += __shfl_xor_sync(0xffffffffu, k, o);
                    }
                    tau = (s - 1.0f) / (float)k;
                    if (k == prev) break;   // active set stable -> fixed point
                    prev = k;
                }
                if (tid == 0) s_tau = tau;
            }
            __syncthreads();
        } else {
            // ---- Fallback: block-wide Michelot over register values ----
            float tau = thr;
            int prev = -1;
            for (int it = 0; it < D + 2; it++) {
                float s = 0.0f; int k = 0;
                float vals[16] = {c0.x, c0.y, c0.z, c0.w, c1.x, c1.y, c1.z, c1.w,
                                  c2.x, c2.y, c2.z, c2.w, c3.x, c3.y, c3.z, c3.w};
                #pragma unroll
                for (int i = 0; i < 16; i++)
                    if (vals[i] > tau) { s += vals[i]; k++; }
                #pragma unroll
                for (int o = 16; o > 0; o >>= 1) {
                    s += __shfl_xor_sync(0xffffffffu, s, o);
                    k += __shfl_xor_sync(0xffffffffu, k, o);
                }
                if (lid == 0) { sredf[tid >> 5] = s; sredk[tid >> 5] = k; }
                __syncthreads();
                if (tid == 0) {
                    float S = 0.0f; int K = 0;
                    #pragma unroll
                    for (int w = 0; w < NWARPS; w++) { S += sredf[w]; K += sredk[w]; }
                    s_tau = (S - 1.0f) / (float)K;
                    s_k = K;
                }
                __syncthreads();
                tau = s_tau;
                int K = s_k;
                if (K == prev) break;
                prev = K;
            }
            __syncthreads();
        }

        if (tid == 0) s_cnt = 0;   // next gather is >2 barriers away

        // ---- write relu(x - tau) from registers (streaming stores) ----
        const float tau = s_tau;
        c0.x = fmaxf(c0.x - tau, 0.0f); c0.y = fmaxf(c0.y - tau, 0.0f);
        c0.z = fmaxf(c0.z - tau, 0.0f); c0.w = fmaxf(c0.w - tau, 0.0f);
        c1.x = fmaxf(c1.x - tau, 0.0f); c1.y = fmaxf(c1.y - tau, 0.0f);
        c1.z = fmaxf(c1.z - tau, 0.0f); c1.w = fmaxf(c1.w - tau, 0.0f);
        c2.x = fmaxf(c2.x - tau, 0.0f); c2.y = fmaxf(c2.y - tau, 0.0f);
        c2.z = fmaxf(c2.z - tau, 0.0f); c2.w = fmaxf(c2.w - tau, 0.0f);
        c3.x = fmaxf(c3.x - tau, 0.0f); c3.y = fmaxf(c3.y - tau, 0.0f);
        c3.z = fmaxf(c3.z - tau, 0.0f); c3.w = fmaxf(c3.w - tau, 0.0f);
        float4* __restrict__ xout = reinterpret_cast<float4*>(out + (size_t)r * D);
        __stcs(&xout[tid],               c0);
        __stcs(&xout[tid + THREADS],     c1);
        __stcs(&xout[tid + 2 * THREADS], c2);
        __stcs(&xout[tid + 3 * THREADS], c3);

        if (!has_next) break;
        cur ^= 1;
        r = rn;
    }
}

extern "C" void kernel_launch(void* const* d_in, const int* in_sizes, int n_in,
                              void* d_out, int out_size) {
    const float* x = (const float*)d_in[0];
    float* out = (float*)d_out;
    const int rows = in_sizes[0] / D;   // 8192

    const int dyn_smem = 2 * D * (int)sizeof(float);   // 64 KB double buffer
    cudaFuncSetAttribute(sparsemax_kernel,
                         cudaFuncAttributeMaxDynamicSharedMemorySize, dyn_smem);

    int dev = 0;
    cudaGetDevice(&dev);
    int nsm = 148;
    cudaDeviceGetAttribute(&nsm, cudaDevAttrMultiProcessorCount, dev);
    int grid = nsm * 3;                 // 3 CTAs/SM, persistent, static strided rows
    if (grid > rows) grid = rows;

    sparsemax_kernel<<<grid, THREADS, dyn_smem>>>(x, out, rows);
}